// round 2
// baseline (speedup 1.0000x reference)
#include <cuda_runtime.h>
#include <cuda_bf16.h>
#include <math.h>

// ---------------------------------------------------------------------------
// Problem constants (fixed shapes from setup_inputs)
// ---------------------------------------------------------------------------
#define BB 4
#define PHI_K 1792
#define NPIX 4096            // 64*64
#define MROWS (BB*NPIX)      // 16384
#define NCENT 4096
#define NTOP 200

// ---------------------------------------------------------------------------
// Scratch (static device globals; referenced directly from device code so
// kernel_launch makes NO runtime API calls besides kernel launches)
// ---------------------------------------------------------------------------
__device__ float g_pool0[BB*256*64*64];
__device__ float g_pool1[BB*512*32*32];
__device__ float g_pool2[BB*1024*16*16];
__device__ float g_conv0[BB*256*64*64];
__device__ float g_conv1[BB*512*32*32];
__device__ float g_conv2[BB*1024*16*16];
__device__ float g_phi[(size_t)MROWS*PHI_K];     // row-major [row][k]
__device__ float g_feats[MROWS];
__device__ float g_cents[NCENT];
__device__ float g_dist[(size_t)MROWS*NCENT];    // 268 MB

// ---------------------------------------------------------------------------
// 3x3 average pool, stride 1, pad 1, count_include_pad (divide by 9)
// ---------------------------------------------------------------------------
template<int SEL>
__global__ void pool3_kernel(const float* __restrict__ in, int C, int H, int W) {
    float* out = (SEL == 0) ? g_pool0 : (SEL == 1) ? g_pool1 : g_pool2;
    int idx = blockIdx.x * blockDim.x + threadIdx.x;
    int total = BB * C * H * W;
    if (idx >= total) return;
    int w = idx % W;
    int h = (idx / W) % H;
    int bc = idx / (W * H);
    const float* p = in + (size_t)bc * H * W;
    float s = 0.f;
    #pragma unroll
    for (int dy = -1; dy <= 1; dy++) {
        int y = h + dy;
        if (y < 0 || y >= H) continue;
        #pragma unroll
        for (int dx = -1; dx <= 1; dx++) {
            int x = w + dx;
            if (x < 0 || x >= W) continue;
            s += p[y * W + x];
        }
    }
    out[idx] = s * (1.0f / 9.0f);
}

// ---------------------------------------------------------------------------
// CoordConv 1x1: O[b,o,h,w] = sum_c W[o,c]*A[b,c,h,w] + W[o,C]*xg + W[o,C+1]*yg + b[o]
// Tiled GEMM: 64 outputs x 64 pixels per block, BK=16, 256 threads, 4x4/thread.
// ---------------------------------------------------------------------------
template<int SEL>
__global__ void conv1x1_kernel(const float* __restrict__ Wt,
                               const float* __restrict__ bias,
                               int Cin, int Cout, int H, int W) {
    const float* A = (SEL == 0) ? g_pool0 : (SEL == 1) ? g_pool1 : g_pool2;
    float* O = (SEL == 0) ? g_conv0 : (SEL == 1) ? g_conv1 : g_conv2;
    int npix = H * W;
    int b = blockIdx.z;
    int pbase = blockIdx.x * 64;
    int obase = blockIdx.y * 64;
    __shared__ float As[16][64];
    __shared__ float Ws[64][17];
    int tid = threadIdx.x;
    int tr = tid / 16, tc = tid % 16;
    float acc[4][4] = {};
    int ldw = Cin + 2;

    for (int k0 = 0; k0 < Cin; k0 += 16) {
        for (int t = tid; t < 64 * 16; t += 256) {
            int o = t / 16, kc = t % 16;
            Ws[o][kc] = Wt[(size_t)(obase + o) * ldw + k0 + kc];
        }
        for (int t = tid; t < 16 * 64; t += 256) {
            int kc = t / 64, p = t % 64;
            As[kc][p] = A[((size_t)(b * Cin + k0 + kc)) * npix + pbase + p];
        }
        __syncthreads();
        #pragma unroll
        for (int kc = 0; kc < 16; kc++) {
            float wv[4], av[4];
            #pragma unroll
            for (int i = 0; i < 4; i++) wv[i] = Ws[tr * 4 + i][kc];
            #pragma unroll
            for (int j = 0; j < 4; j++) av[j] = As[kc][tc * 4 + j];
            #pragma unroll
            for (int i = 0; i < 4; i++)
                #pragma unroll
                for (int j = 0; j < 4; j++) acc[i][j] += wv[i] * av[j];
        }
        __syncthreads();
    }

    float inv_w = 2.0f / (float)(W - 1);
    float inv_h = 2.0f / (float)(H - 1);
    #pragma unroll
    for (int i = 0; i < 4; i++) {
        int o = obase + tr * 4 + i;
        float wx = Wt[(size_t)o * ldw + Cin];
        float wy = Wt[(size_t)o * ldw + Cin + 1];
        float bb = bias[o];
        #pragma unroll
        for (int j = 0; j < 4; j++) {
            int p = pbase + tc * 4 + j;
            int h = p / W, w = p % W;
            float xg = -1.0f + inv_w * (float)w;
            float yg = -1.0f + inv_h * (float)h;
            O[((size_t)(b * Cout + o)) * npix + p] = acc[i][j] + wx * xg + wy * yg + bb;
        }
    }
}

// ---------------------------------------------------------------------------
// Bilinear resize to 64x64 (half-pixel centers + edge clamp == JAX triangle
// resize with weight renormalization for radius-1 upsampling) into:
//   - g_phi [row=b*4096+pix][ch_base+k]
//   - d_out second output (PHI channels < 896) in (b,c,h,w) layout
// ---------------------------------------------------------------------------
template<int SEL>
__global__ void resize_kernel(int Co, int Hin, int ch_base, float* __restrict__ out2) {
    const float* O = (SEL == 0) ? g_conv0 : (SEL == 1) ? g_conv1 : g_conv2;
    long long idx = (long long)blockIdx.x * blockDim.x + threadIdx.x;
    long long total = (long long)BB * NPIX * Co;
    if (idx >= total) return;
    int k = (int)(idx % Co);
    int pix = (int)((idx / Co) % NPIX);
    int b = (int)(idx / ((long long)Co * NPIX));
    int y = pix >> 6, x = pix & 63;
    int Win = Hin;
    int npix_in = Hin * Win;
    float scale = (float)Hin / 64.0f;
    float fy = ((float)y + 0.5f) * scale - 0.5f;
    float fx = ((float)x + 0.5f) * scale - 0.5f;
    int y0 = (int)floorf(fy); float wy1 = fy - (float)y0;
    int x0 = (int)floorf(fx); float wx1 = fx - (float)x0;
    int y0c = min(max(y0, 0), Hin - 1), y1c = min(max(y0 + 1, 0), Hin - 1);
    int x0c = min(max(x0, 0), Win - 1), x1c = min(max(x0 + 1, 0), Win - 1);
    const float* base = O + ((size_t)(b * Co + k)) * npix_in;
    float v00 = base[y0c * Win + x0c], v01 = base[y0c * Win + x1c];
    float v10 = base[y1c * Win + x0c], v11 = base[y1c * Win + x1c];
    float v = (1.0f - wy1) * ((1.0f - wx1) * v00 + wx1 * v01)
            + wy1 * ((1.0f - wx1) * v10 + wx1 * v11);
    int row = b * NPIX + pix;
    g_phi[(size_t)row * PHI_K + ch_base + k] = v;
    int cg = ch_base + k;
    if (cg < 896) {
        out2[((size_t)(b * 896 + cg)) * NPIX + pix] = v;
    }
}

// ---------------------------------------------------------------------------
// Per-row ||phi||^2
// ---------------------------------------------------------------------------
__global__ void feats_kernel() {
    int row = blockIdx.x;
    const float* p = g_phi + (size_t)row * PHI_K;
    float s = 0.f;
    for (int k = threadIdx.x; k < PHI_K; k += 256) {
        float v = p[k];
        s += v * v;
    }
    __shared__ float red[256];
    red[threadIdx.x] = s;
    __syncthreads();
    for (int off = 128; off > 0; off >>= 1) {
        if (threadIdx.x < off) red[threadIdx.x] += red[threadIdx.x + off];
        __syncthreads();
    }
    if (threadIdx.x == 0) g_feats[row] = red[0];
}

// ---------------------------------------------------------------------------
// Per-column ||c||^2 of C (1792 x 4096)
// ---------------------------------------------------------------------------
__global__ void cents_kernel(const float* __restrict__ C) {
    int col = blockIdx.x * blockDim.x + threadIdx.x;
    if (col >= NCENT) return;
    float s = 0.f;
    for (int k = 0; k < PHI_K; k++) {
        float v = C[(size_t)k * NCENT + col];
        s += v * v;
    }
    g_cents[col] = s;
}

// ---------------------------------------------------------------------------
// Distance GEMM: D[m][n] = sqrt(max(feats[m] + cents[n] - 2*sum_k phi[m,k]*C[k,n], 0))
// 128x128 tile, BK=8, 256 threads, 8x8 per thread.
// ---------------------------------------------------------------------------
__global__ void __launch_bounds__(256, 2)
dist_gemm_kernel(const float* __restrict__ Bm) {
    __shared__ float As[8][132];
    __shared__ float Bs[8][128];
    int tid = threadIdx.x;
    int mbase = blockIdx.y * 128, nbase = blockIdx.x * 128;
    int tr = tid / 16, tc = tid % 16;
    float acc[8][8] = {};

    int a_m = tid >> 1;
    int a_k4 = (tid & 1) * 4;
    int b_k = tid >> 5;
    int b_n4 = (tid & 31) * 4;

    for (int k0 = 0; k0 < PHI_K; k0 += 8) {
        float4 av = *(const float4*)&g_phi[(size_t)(mbase + a_m) * PHI_K + k0 + a_k4];
        float4 bv = *(const float4*)&Bm[(size_t)(k0 + b_k) * NCENT + nbase + b_n4];
        As[a_k4 + 0][a_m] = av.x;
        As[a_k4 + 1][a_m] = av.y;
        As[a_k4 + 2][a_m] = av.z;
        As[a_k4 + 3][a_m] = av.w;
        *(float4*)&Bs[b_k][b_n4] = bv;
        __syncthreads();
        #pragma unroll
        for (int kk = 0; kk < 8; kk++) {
            float ar[8], br[8];
            #pragma unroll
            for (int i = 0; i < 8; i++) ar[i] = As[kk][tr * 8 + i];
            #pragma unroll
            for (int j = 0; j < 8; j++) br[j] = Bs[kk][tc * 8 + j];
            #pragma unroll
            for (int i = 0; i < 8; i++)
                #pragma unroll
                for (int j = 0; j < 8; j++) acc[i][j] += ar[i] * br[j];
        }
        __syncthreads();
    }

    float fr[8], cn[8];
    #pragma unroll
    for (int i = 0; i < 8; i++) fr[i] = g_feats[mbase + tr * 8 + i];
    #pragma unroll
    for (int j = 0; j < 8; j++) cn[j] = g_cents[nbase + tc * 8 + j];
    #pragma unroll
    for (int i = 0; i < 8; i++) {
        int m = mbase + tr * 8 + i;
        #pragma unroll
        for (int j = 0; j < 8; j++) {
            int n = nbase + tc * 8 + j;
            float d2 = fr[i] + cn[j] - 2.0f * acc[i][j];
            g_dist[(size_t)m * NCENT + n] = sqrtf(fmaxf(d2, 0.0f));
        }
    }
}

// ---------------------------------------------------------------------------
// Per-row sorted top-200 smallest: bitonic sort of 4096 keys in shared memory.
// Writes score[b, k, h, w] = k-th smallest distance.
// ---------------------------------------------------------------------------
__global__ void __launch_bounds__(512)
topk_kernel(float* __restrict__ out) {
    __shared__ float s[4096];
    int row = blockIdx.x;
    const float* d = g_dist + (size_t)row * NCENT;
    for (int i = threadIdx.x; i < 4096; i += 512) s[i] = d[i];
    __syncthreads();
    for (int k = 2; k <= 4096; k <<= 1) {
        for (int j = k >> 1; j > 0; j >>= 1) {
            for (int i = threadIdx.x; i < 4096; i += 512) {
                int ixj = i ^ j;
                if (ixj > i) {
                    bool up = (i & k) == 0;
                    float a = s[i], b = s[ixj];
                    if ((a > b) == up) { s[i] = b; s[ixj] = a; }
                }
            }
            __syncthreads();
        }
    }
    int b = row >> 12;
    int pix = row & 4095;
    for (int kk = threadIdx.x; kk < NTOP; kk += 512) {
        out[((size_t)(b * NTOP + kk)) * NPIX + pix] = s[kk];
    }
}

// ---------------------------------------------------------------------------
// Launch
// Inputs: 0:p0 1:p1 2:p2 3:label 4:mask 5:w1 6:b1 7:w2 8:b2 9:w3 10:b3 11:C
// Output: [score (4*200*4096)] ++ [PHI[:, :896] (4*896*4096)]
// ---------------------------------------------------------------------------
extern "C" void kernel_launch(void* const* d_in, const int* in_sizes, int n_in,
                              void* d_out, int out_size) {
    const float* p0 = (const float*)d_in[0];
    const float* p1 = (const float*)d_in[1];
    const float* p2 = (const float*)d_in[2];
    const float* w1 = (const float*)d_in[5];
    const float* b1 = (const float*)d_in[6];
    const float* w2 = (const float*)d_in[7];
    const float* b2 = (const float*)d_in[8];
    const float* w3 = (const float*)d_in[9];
    const float* b3 = (const float*)d_in[10];
    const float* C  = (const float*)d_in[11];
    float* out = (float*)d_out;
    float* out_score = out;
    float* out_phi = out + (size_t)BB * NTOP * NPIX;

    // 1) avg pool per level
    {
        int t0 = BB * 256 * 64 * 64;
        pool3_kernel<0><<<(t0 + 255) / 256, 256>>>(p0, 256, 64, 64);
        int t1 = BB * 512 * 32 * 32;
        pool3_kernel<1><<<(t1 + 255) / 256, 256>>>(p1, 512, 32, 32);
        int t2 = BB * 1024 * 16 * 16;
        pool3_kernel<2><<<(t2 + 255) / 256, 256>>>(p2, 1024, 16, 16);
    }

    // 2) coord conv per level
    conv1x1_kernel<0><<<dim3(64 * 64 / 64, 256 / 64, BB), 256>>>(w1, b1, 256, 256, 64, 64);
    conv1x1_kernel<1><<<dim3(32 * 32 / 64, 512 / 64, BB), 256>>>(w2, b2, 512, 512, 32, 32);
    conv1x1_kernel<2><<<dim3(16 * 16 / 64, 1024 / 64, BB), 256>>>(w3, b3, 1024, 1024, 16, 16);

    // 3) resize into phi (+ second output slice)
    {
        long long t0 = (long long)BB * NPIX * 256;
        resize_kernel<0><<<(unsigned)((t0 + 255) / 256), 256>>>(256, 64, 0, out_phi);
        long long t1 = (long long)BB * NPIX * 512;
        resize_kernel<1><<<(unsigned)((t1 + 255) / 256), 256>>>(512, 32, 256, out_phi);
        long long t2 = (long long)BB * NPIX * 1024;
        resize_kernel<2><<<(unsigned)((t2 + 255) / 256), 256>>>(1024, 16, 768, out_phi);
    }

    // 4) norms
    feats_kernel<<<MROWS, 256>>>();
    cents_kernel<<<NCENT / 256, 256>>>(C);

    // 5) distance GEMM with fused sqrt epilogue
    dist_gemm_kernel<<<dim3(NCENT / 128, MROWS / 128), 256>>>(C);

    // 6) per-row sorted top-200
    topk_kernel<<<MROWS, 512>>>(out_score);
}

// round 3
// speedup vs baseline: 3.6706x; 3.6706x over previous
#include <cuda_runtime.h>
#include <cuda_bf16.h>
#include <math.h>
#include <stdint.h>

// ---------------------------------------------------------------------------
// Problem constants
// ---------------------------------------------------------------------------
#define BB 4
#define PHI_K 1792
#define NPIX 4096
#define MROWS (BB*NPIX)      // 16384
#define NCENT 4096
#define NTOP 200

// ---------------------------------------------------------------------------
// Static device scratch
// ---------------------------------------------------------------------------
__device__ float g_pool0[BB*256*64*64];
__device__ float g_pool1[BB*512*32*32];
__device__ float g_pool2[BB*1024*16*16];
__device__ float g_conv0[BB*256*64*64];
__device__ float g_conv1[BB*512*32*32];
__device__ float g_conv2[BB*1024*16*16];
__device__ __nv_bfloat16 g_phib[(size_t)MROWS*PHI_K];  // [row][k] bf16
__device__ __nv_bfloat16 g_Cb[(size_t)PHI_K*NCENT];    // [k][n] bf16
__device__ float g_feats[MROWS];
__device__ float g_cents[NCENT];
__device__ float g_dist[(size_t)MROWS*NCENT];          // 268 MB

// ---------------------------------------------------------------------------
// PTX helpers: ldmatrix + bf16 mma
// ---------------------------------------------------------------------------
__device__ __forceinline__ void ldsm4(uint32_t* r, uint32_t saddr) {
    asm volatile("ldmatrix.sync.aligned.m8n8.x4.shared.b16 {%0,%1,%2,%3}, [%4];"
                 : "=r"(r[0]), "=r"(r[1]), "=r"(r[2]), "=r"(r[3]) : "r"(saddr));
}
__device__ __forceinline__ void ldsm4t(uint32_t* r, uint32_t saddr) {
    asm volatile("ldmatrix.sync.aligned.m8n8.x4.trans.shared.b16 {%0,%1,%2,%3}, [%4];"
                 : "=r"(r[0]), "=r"(r[1]), "=r"(r[2]), "=r"(r[3]) : "r"(saddr));
}
__device__ __forceinline__ void mma16816(float* d, const uint32_t* a, const uint32_t* b) {
    asm volatile("mma.sync.aligned.m16n8k16.row.col.f32.bf16.bf16.f32 "
                 "{%0,%1,%2,%3}, {%4,%5,%6,%7}, {%8,%9}, {%0,%1,%2,%3};"
                 : "+f"(d[0]), "+f"(d[1]), "+f"(d[2]), "+f"(d[3])
                 : "r"(a[0]), "r"(a[1]), "r"(a[2]), "r"(a[3]),
                   "r"(b[0]), "r"(b[1]));
}

// ---------------------------------------------------------------------------
// 3x3 avg pool, stride 1, pad 1 (divide by 9)
// ---------------------------------------------------------------------------
template<int SEL>
__global__ void pool3_kernel(const float* __restrict__ in, int C, int H, int W) {
    float* out = (SEL == 0) ? g_pool0 : (SEL == 1) ? g_pool1 : g_pool2;
    int idx = blockIdx.x * blockDim.x + threadIdx.x;
    int total = BB * C * H * W;
    if (idx >= total) return;
    int w = idx % W;
    int h = (idx / W) % H;
    int bc = idx / (W * H);
    const float* p = in + (size_t)bc * H * W;
    float s = 0.f;
    #pragma unroll
    for (int dy = -1; dy <= 1; dy++) {
        int y = h + dy;
        if (y < 0 || y >= H) continue;
        #pragma unroll
        for (int dx = -1; dx <= 1; dx++) {
            int x = w + dx;
            if (x < 0 || x >= W) continue;
            s += p[y * W + x];
        }
    }
    out[idx] = s * (1.0f / 9.0f);
}

// ---------------------------------------------------------------------------
// CoordConv 1x1 (tiled fp32 GEMM, 64x64 tiles)
// ---------------------------------------------------------------------------
template<int SEL>
__global__ void conv1x1_kernel(const float* __restrict__ Wt,
                               const float* __restrict__ bias,
                               int Cin, int Cout, int H, int W) {
    const float* A = (SEL == 0) ? g_pool0 : (SEL == 1) ? g_pool1 : g_pool2;
    float* O = (SEL == 0) ? g_conv0 : (SEL == 1) ? g_conv1 : g_conv2;
    int npix = H * W;
    int b = blockIdx.z;
    int pbase = blockIdx.x * 64;
    int obase = blockIdx.y * 64;
    __shared__ float As[16][64];
    __shared__ float Ws[64][17];
    int tid = threadIdx.x;
    int tr = tid / 16, tc = tid % 16;
    float acc[4][4] = {};
    int ldw = Cin + 2;

    for (int k0 = 0; k0 < Cin; k0 += 16) {
        for (int t = tid; t < 64 * 16; t += 256) {
            int o = t / 16, kc = t % 16;
            Ws[o][kc] = Wt[(size_t)(obase + o) * ldw + k0 + kc];
        }
        for (int t = tid; t < 16 * 64; t += 256) {
            int kc = t / 64, p = t % 64;
            As[kc][p] = A[((size_t)(b * Cin + k0 + kc)) * npix + pbase + p];
        }
        __syncthreads();
        #pragma unroll
        for (int kc = 0; kc < 16; kc++) {
            float wv[4], av[4];
            #pragma unroll
            for (int i = 0; i < 4; i++) wv[i] = Ws[tr * 4 + i][kc];
            #pragma unroll
            for (int j = 0; j < 4; j++) av[j] = As[kc][tc * 4 + j];
            #pragma unroll
            for (int i = 0; i < 4; i++)
                #pragma unroll
                for (int j = 0; j < 4; j++) acc[i][j] += wv[i] * av[j];
        }
        __syncthreads();
    }

    float inv_w = 2.0f / (float)(W - 1);
    float inv_h = 2.0f / (float)(H - 1);
    #pragma unroll
    for (int i = 0; i < 4; i++) {
        int o = obase + tr * 4 + i;
        float wx = Wt[(size_t)o * ldw + Cin];
        float wy = Wt[(size_t)o * ldw + Cin + 1];
        float bb = bias[o];
        #pragma unroll
        for (int j = 0; j < 4; j++) {
            int p = pbase + tc * 4 + j;
            int h = p / W, w = p % W;
            float xg = -1.0f + inv_w * (float)w;
            float yg = -1.0f + inv_h * (float)h;
            O[((size_t)(b * Cout + o)) * npix + p] = acc[i][j] + wx * xg + wy * yg + bb;
        }
    }
}

// ---------------------------------------------------------------------------
// Bilinear resize -> g_phib (bf16) + second output (fp32, channels < 896)
// ---------------------------------------------------------------------------
template<int SEL>
__global__ void resize_kernel(int Co, int Hin, int ch_base, float* __restrict__ out2) {
    const float* O = (SEL == 0) ? g_conv0 : (SEL == 1) ? g_conv1 : g_conv2;
    long long idx = (long long)blockIdx.x * blockDim.x + threadIdx.x;
    long long total = (long long)BB * NPIX * Co;
    if (idx >= total) return;
    int k = (int)(idx % Co);
    int pix = (int)((idx / Co) % NPIX);
    int b = (int)(idx / ((long long)Co * NPIX));
    int y = pix >> 6, x = pix & 63;
    int Win = Hin;
    int npix_in = Hin * Win;
    float scale = (float)Hin / 64.0f;
    float fy = ((float)y + 0.5f) * scale - 0.5f;
    float fx = ((float)x + 0.5f) * scale - 0.5f;
    int y0 = (int)floorf(fy); float wy1 = fy - (float)y0;
    int x0 = (int)floorf(fx); float wx1 = fx - (float)x0;
    int y0c = min(max(y0, 0), Hin - 1), y1c = min(max(y0 + 1, 0), Hin - 1);
    int x0c = min(max(x0, 0), Win - 1), x1c = min(max(x0 + 1, 0), Win - 1);
    const float* base = O + ((size_t)(b * Co + k)) * npix_in;
    float v00 = base[y0c * Win + x0c], v01 = base[y0c * Win + x1c];
    float v10 = base[y1c * Win + x0c], v11 = base[y1c * Win + x1c];
    float v = (1.0f - wy1) * ((1.0f - wx1) * v00 + wx1 * v01)
            + wy1 * ((1.0f - wx1) * v10 + wx1 * v11);
    int row = b * NPIX + pix;
    g_phib[(size_t)row * PHI_K + ch_base + k] = __float2bfloat16(v);
    int cg = ch_base + k;
    if (cg < 896) {
        out2[((size_t)(b * 896 + cg)) * NPIX + pix] = v;
    }
}

// ---------------------------------------------------------------------------
// Convert C to bf16
// ---------------------------------------------------------------------------
__global__ void convC_kernel(const float* __restrict__ C) {
    size_t i = (size_t)blockIdx.x * blockDim.x + threadIdx.x;
    size_t total = (size_t)PHI_K * NCENT;
    if (i < total) g_Cb[i] = __float2bfloat16(C[i]);
}

// ---------------------------------------------------------------------------
// Per-row ||phi_b||^2 (from bf16, fp32 accumulate — consistent with GEMM)
// ---------------------------------------------------------------------------
__global__ void feats_kernel() {
    int row = blockIdx.x;
    const __nv_bfloat16* p = g_phib + (size_t)row * PHI_K;
    float s = 0.f;
    for (int k = threadIdx.x; k < PHI_K; k += 256) {
        float v = __bfloat162float(p[k]);
        s += v * v;
    }
    __shared__ float red[256];
    red[threadIdx.x] = s;
    __syncthreads();
    for (int off = 128; off > 0; off >>= 1) {
        if (threadIdx.x < off) red[threadIdx.x] += red[threadIdx.x + off];
        __syncthreads();
    }
    if (threadIdx.x == 0) g_feats[row] = red[0];
}

// ---------------------------------------------------------------------------
// Per-column ||c_b||^2 (from bf16)
// ---------------------------------------------------------------------------
__global__ void cents_kernel() {
    int col = blockIdx.x * blockDim.x + threadIdx.x;
    if (col >= NCENT) return;
    float s = 0.f;
    for (int k = 0; k < PHI_K; k++) {
        float v = __bfloat162float(g_Cb[(size_t)k * NCENT + col]);
        s += v * v;
    }
    g_cents[col] = s;
}

// ---------------------------------------------------------------------------
// bf16 tensor-core distance GEMM.
// Block tile 128(M) x 128(N), K-step 16, 256 threads = 8 warps (2x4),
// warp tile 64x32. mma.sync.m16n8k16 bf16 -> fp32.
// D[m][n] = sqrt(max(feats[m] + cents[n] - 2*dot, 0))
// ---------------------------------------------------------------------------
__global__ void __launch_bounds__(256, 2)
dist_gemm_bf16_kernel() {
    __shared__ __nv_bfloat16 As[128][24];   // pad 8 -> 48B rows (conflict-free ldmatrix)
    __shared__ __nv_bfloat16 Bs[16][136];   // pad 8 -> 272B rows

    int tid = threadIdx.x;
    int lane = tid & 31, warp = tid >> 5;
    int wm = warp >> 2, wn = warp & 3;
    int mbase = blockIdx.y * 128, nbase = blockIdx.x * 128;

    // global load slots (one float4 = 8 bf16 per thread per tile)
    int arow = tid >> 1, akof = (tid & 1) * 8;
    int brow = tid >> 4, bnof = (tid & 15) * 8;
    const __nv_bfloat16* AG = g_phib + (size_t)(mbase + arow) * PHI_K + akof;
    const __nv_bfloat16* BG = g_Cb + (size_t)brow * NCENT + nbase + bnof;

    // ldmatrix per-lane base addresses
    uint32_t a_base = (uint32_t)__cvta_generic_to_shared(
        &As[wm * 64 + (lane & 15)][(lane >> 4) * 8]);
    uint32_t b_base = (uint32_t)__cvta_generic_to_shared(
        &Bs[lane & 15][wn * 32 + (lane >> 4) * 8]);

    float acc[4][4][4];
    #pragma unroll
    for (int i = 0; i < 4; i++)
        #pragma unroll
        for (int j = 0; j < 4; j++)
            #pragma unroll
            for (int e = 0; e < 4; e++) acc[i][j][e] = 0.f;

    float4 ra = *(const float4*)AG;
    float4 rb = *(const float4*)BG;

    const int NIT = PHI_K / 16;  // 112
    for (int it = 0; it < NIT; it++) {
        *(float4*)&As[arow][akof] = ra;
        *(float4*)&Bs[brow][bnof] = rb;
        __syncthreads();
        if (it + 1 < NIT) {
            ra = *(const float4*)(AG + (size_t)(it + 1) * 16);
            rb = *(const float4*)(BG + (size_t)(it + 1) * 16 * NCENT);
        }
        uint32_t a[4][4];
        uint32_t bf[4][2];
        #pragma unroll
        for (int fm = 0; fm < 4; fm++)
            ldsm4(a[fm], a_base + fm * 16 * 48);      // 16 rows * 48 bytes
        {
            uint32_t t0[4], t1[4];
            ldsm4t(t0, b_base);                        // n-cols [wn*32, wn*32+16)
            ldsm4t(t1, b_base + 32);                   // +16 bf16 = 32 bytes
            bf[0][0] = t0[0]; bf[0][1] = t0[1];
            bf[1][0] = t0[2]; bf[1][1] = t0[3];
            bf[2][0] = t1[0]; bf[2][1] = t1[1];
            bf[3][0] = t1[2]; bf[3][1] = t1[3];
        }
        #pragma unroll
        for (int fm = 0; fm < 4; fm++)
            #pragma unroll
            for (int fn = 0; fn < 4; fn++)
                mma16816(acc[fm][fn], a[fm], bf[fn]);
        __syncthreads();
    }

    // epilogue: d = sqrt(max(f + c - 2*dot, 0))
    int r = lane >> 2, c = lane & 3;
    #pragma unroll
    for (int fm = 0; fm < 4; fm++) {
        int m0 = mbase + wm * 64 + fm * 16;
        float f0 = g_feats[m0 + r];
        float f1 = g_feats[m0 + r + 8];
        #pragma unroll
        for (int fn = 0; fn < 4; fn++) {
            int n0 = nbase + wn * 32 + fn * 8 + c * 2;
            float cn0 = g_cents[n0], cn1 = g_cents[n0 + 1];
            float2 lo, hi;
            lo.x = sqrtf(fmaxf(f0 + cn0 - 2.f * acc[fm][fn][0], 0.f));
            lo.y = sqrtf(fmaxf(f0 + cn1 - 2.f * acc[fm][fn][1], 0.f));
            hi.x = sqrtf(fmaxf(f1 + cn0 - 2.f * acc[fm][fn][2], 0.f));
            hi.y = sqrtf(fmaxf(f1 + cn1 - 2.f * acc[fm][fn][3], 0.f));
            *(float2*)&g_dist[(size_t)(m0 + r) * NCENT + n0] = lo;
            *(float2*)&g_dist[(size_t)(m0 + r + 8) * NCENT + n0] = hi;
        }
    }
}

// ---------------------------------------------------------------------------
// Exact top-200 (sorted ascending) per row via 4-pass byte radix-select.
// Positive floats: uint bit pattern is order-preserving.
// One block (256 threads) per row.
// ---------------------------------------------------------------------------
__global__ void __launch_bounds__(256)
topk_kernel(float* __restrict__ out) {
    __shared__ uint32_t keys[4096];
    __shared__ uint32_t whist[8][256];
    __shared__ uint32_t scan_s[256];
    __shared__ int sel_bin, sel_before;
    __shared__ uint32_t s_cnt;
    __shared__ float buf[256];

    int tid = threadIdx.x;
    int lane = tid & 31, warp = tid >> 5;
    int row = blockIdx.x;
    const float* d = g_dist + (size_t)row * NCENT;

    for (int i = tid; i < 4096; i += 256)
        keys[i] = __float_as_uint(d[i]);
    __syncthreads();

    uint32_t prefix = 0, prefMask = 0;
    int rank = NTOP - 1;   // 0-based rank of the 200th smallest
    int L = 0;             // count of keys strictly < T (accumulated)

    for (int p = 3; p >= 0; p--) {
        // zero per-warp histograms
        for (int i = tid; i < 8 * 256; i += 256)
            ((uint32_t*)whist)[i] = 0;
        __syncthreads();

        for (int i = tid; i < 4096; i += 256) {
            uint32_t k = keys[i];
            bool ok = ((k & prefMask) == prefix);
            unsigned act = __ballot_sync(0xffffffffu, ok);
            if (ok) {
                int bin = (k >> (8 * p)) & 255;
                unsigned same = __match_any_sync(act, bin);
                int leader = __ffs(same) - 1;
                if (lane == leader)
                    whist[warp][bin] += __popc(same);
            }
        }
        __syncthreads();

        // reduce 8 warp-hists + inclusive scan over 256 bins
        uint32_t tot = 0;
        #pragma unroll
        for (int w = 0; w < 8; w++) tot += whist[w][tid];
        scan_s[tid] = tot;
        __syncthreads();
        for (int off = 1; off < 256; off <<= 1) {
            uint32_t v = (tid >= off) ? scan_s[tid - off] : 0;
            __syncthreads();
            scan_s[tid] += v;
            __syncthreads();
        }
        int before = (int)scan_s[tid] - (int)tot;
        if (tot > 0 && rank >= before && rank < (int)scan_s[tid]) {
            sel_bin = tid;
            sel_before = before;
        }
        __syncthreads();
        prefix |= ((uint32_t)sel_bin) << (8 * p);
        prefMask |= 0xFFu << (8 * p);
        L += sel_before;
        rank -= sel_before;
        __syncthreads();
    }

    uint32_t T = prefix;   // exact key of the 200th smallest
    if (tid == 0) s_cnt = 0;
    __syncthreads();
    for (int i = tid; i < 4096; i += 256) {
        uint32_t k = keys[i];
        if (k < T) {
            uint32_t pos = atomicAdd(&s_cnt, 1u);
            buf[pos] = __uint_as_float(k);
        }
    }
    __syncthreads();
    // pad with T (handles ties exactly): buf[0..255] multiset's smallest 200
    // equals the row's smallest 200.
    if (tid >= (int)s_cnt) buf[tid] = __uint_as_float(T);
    __syncthreads();

    // bitonic sort 256 ascending (1 element per thread)
    for (int k = 2; k <= 256; k <<= 1) {
        for (int j = k >> 1; j > 0; j >>= 1) {
            int i = tid, ixj = i ^ j;
            if (ixj > i) {
                bool up = (i & k) == 0;
                float a = buf[i], b = buf[ixj];
                if ((a > b) == up) { buf[i] = b; buf[ixj] = a; }
            }
            __syncthreads();
        }
    }

    if (tid < NTOP) {
        int b = row >> 12;
        int pix = row & 4095;
        out[((size_t)(b * NTOP + tid)) * NPIX + pix] = buf[tid];
    }
}

// ---------------------------------------------------------------------------
// Launch
// Inputs: 0:p0 1:p1 2:p2 3:label 4:mask 5:w1 6:b1 7:w2 8:b2 9:w3 10:b3 11:C
// Output: [score (4*200*4096)] ++ [PHI[:, :896] (4*896*4096)]
// ---------------------------------------------------------------------------
extern "C" void kernel_launch(void* const* d_in, const int* in_sizes, int n_in,
                              void* d_out, int out_size) {
    const float* p0 = (const float*)d_in[0];
    const float* p1 = (const float*)d_in[1];
    const float* p2 = (const float*)d_in[2];
    const float* w1 = (const float*)d_in[5];
    const float* b1 = (const float*)d_in[6];
    const float* w2 = (const float*)d_in[7];
    const float* b2 = (const float*)d_in[8];
    const float* w3 = (const float*)d_in[9];
    const float* b3 = (const float*)d_in[10];
    const float* C  = (const float*)d_in[11];
    float* out = (float*)d_out;
    float* out_score = out;
    float* out_phi = out + (size_t)BB * NTOP * NPIX;

    // C -> bf16 (independent; overlaps with descriptor chain)
    {
        size_t total = (size_t)PHI_K * NCENT;
        convC_kernel<<<(unsigned)((total + 255) / 256), 256>>>(C);
    }

    // 1) avg pool per level
    {
        int t0 = BB * 256 * 64 * 64;
        pool3_kernel<0><<<(t0 + 255) / 256, 256>>>(p0, 256, 64, 64);
        int t1 = BB * 512 * 32 * 32;
        pool3_kernel<1><<<(t1 + 255) / 256, 256>>>(p1, 512, 32, 32);
        int t2 = BB * 1024 * 16 * 16;
        pool3_kernel<2><<<(t2 + 255) / 256, 256>>>(p2, 1024, 16, 16);
    }

    // 2) coord conv per level
    conv1x1_kernel<0><<<dim3(64 * 64 / 64, 256 / 64, BB), 256>>>(w1, b1, 256, 256, 64, 64);
    conv1x1_kernel<1><<<dim3(32 * 32 / 64, 512 / 64, BB), 256>>>(w2, b2, 512, 512, 32, 32);
    conv1x1_kernel<2><<<dim3(16 * 16 / 64, 1024 / 64, BB), 256>>>(w3, b3, 1024, 1024, 16, 16);

    // 3) resize into phi (bf16) + second output slice (fp32)
    {
        long long t0 = (long long)BB * NPIX * 256;
        resize_kernel<0><<<(unsigned)((t0 + 255) / 256), 256>>>(256, 64, 0, out_phi);
        long long t1 = (long long)BB * NPIX * 512;
        resize_kernel<1><<<(unsigned)((t1 + 255) / 256), 256>>>(512, 32, 256, out_phi);
        long long t2 = (long long)BB * NPIX * 1024;
        resize_kernel<2><<<(unsigned)((t2 + 255) / 256), 256>>>(1024, 16, 768, out_phi);
    }

    // 4) norms (from bf16, consistent with GEMM operands)
    feats_kernel<<<MROWS, 256>>>();
    cents_kernel<<<NCENT / 256, 256>>>();

    // 5) bf16 tensor-core distance GEMM with fused sqrt epilogue
    dist_gemm_bf16_kernel<<<dim3(NCENT / 128, MROWS / 128), 256>>>();

    // 6) exact sorted top-200 via radix select
    topk_kernel<<<MROWS, 256>>>(out_score);
}